// round 13
// baseline (speedup 1.0000x reference)
#include <cuda_runtime.h>
#include <cuda_bf16.h>
#include <cstdint>

#define HDIM 2048
#define NEXP 64
#define TOPK 8
#define BK   64
#define NIT  (HDIM / BK)     // 32
#define TILE_T 56            // tokens per CTA -> 293 CTAs, one balanced wave

typedef unsigned long long ull;

// d.lo = fma(a.lo,b.lo,d.lo); d.hi = fma(a.hi,b.hi,d.hi).
__device__ __forceinline__ void ffma2(ull &d, ull a, ull b) {
    asm("fma.rn.f32x2 %0, %1, %2, %0;" : "+l"(d) : "l"(a), "l"(b));
}
__device__ __forceinline__ void cpa16(uint32_t s, const void* g) {
    asm volatile("cp.async.cg.shared.global [%0], [%1], 16;" :: "r"(s), "l"(g));
}
__device__ __forceinline__ void cpa4(uint32_t s, const void* g) {
    asm volatile("cp.async.ca.shared.global [%0], [%1], 4;" :: "r"(s), "l"(g));
}
__device__ __forceinline__ void cpa_commit() {
    asm volatile("cp.async.commit_group;");
}
template <int N>
__device__ __forceinline__ void cpa_wait() {
    asm volatile("cp.async.wait_group %0;" :: "n"(N));
}
__device__ __forceinline__ uint32_t s2u(const void* p) {
    return (uint32_t)__cvta_generic_to_shared(p);
}

// k-major, per-expert DUPLICATED copy of gate_w: gwTdup[k][e] = (w, w) as u64.
__device__ ull g_gwTdup[HDIM * NEXP];

__global__ void transpose_gw(const float* __restrict__ gw) {
    __shared__ float t[32][33];
    int k0 = blockIdx.x * 32, e0 = blockIdx.y * 32;
#pragma unroll
    for (int r = 0; r < 32; r += 8)
        t[threadIdx.y + r][threadIdx.x] =
            gw[(size_t)(e0 + threadIdx.y + r) * HDIM + k0 + threadIdx.x];
    __syncthreads();
#pragma unroll
    for (int r = 0; r < 32; r += 8) {
        float w = t[threadIdx.x][threadIdx.y + r];
        ull d; asm("mov.b64 %0, {%1, %1};" : "=l"(d) : "f"(w));
        g_gwTdup[(size_t)(k0 + threadIdx.y + r) * NEXP + e0 + threadIdx.x] = d;
    }
}

#define ATPAD 68   // floats per At row (16B-aligned rows; 272B stride)
#define BDPAD 66   // ull per Bd row (528B stride, 16B-aligned)

struct Smem {
    union {
        float At[2][BK][ATPAD];      // 34816 B  A TRANSPOSED: row k, col token
        float logits[64][65];        // 16640 B  (aliases At after GEMM)
    };
    ull  Bd[2][BK][BDPAD];           // 67584 B  duplicated B: row k, col expert
    float bias[NEXP];
};
// ~100.3 KB -> dynamic smem; 2 CTAs/SM fit the 228 KB carveout

__global__ __launch_bounds__(256)
void router_kernel(const float* __restrict__ hs,
                   const float* __restrict__ bias,
                   float* __restrict__ out, int T)
{
    extern __shared__ char smem_raw[];
    Smem& sm = *reinterpret_cast<Smem*>(smem_raw);
    const int tid = threadIdx.x;
    const int tx  = tid & 15;        // experts 4tx..4tx+3
    const int ty  = tid >> 4;        // tokens  4ty..4ty+3 (ty 0..15)
    const int t0  = blockIdx.x * TILE_T;

    if (tid < NEXP) sm.bias[tid] = bias[tid];

    // fill tile 'buf' with k-range [kk, kk+64)
    auto fill = [&](int buf, int kk) {
        // At: 64 k-rows x 64 tokens, 4B copies. Lanes run along k -> global
        // reads 128B-coalesced; smem writes stride 272B (4-way conflict, paid
        // once per element vs many reads).
#pragma unroll
        for (int m = 0; m < 16; m++) {
            int idx = tid + 256 * m;
            int k = idx & 63, tok = idx >> 6;
            int trow = t0 + tok; if (trow > T - 1) trow = T - 1;
            cpa4(s2u(&sm.At[buf][k][tok]),
                 &hs[(size_t)trow * HDIM + kk + k]);
        }
        // Bd: 64 k-rows x 64 dup-experts (512B/row), 16B copies.
#pragma unroll
        for (int m = 0; m < 8; m++) {
            int idx = tid + 256 * m;
            int k = idx >> 5, c = idx & 31;          // c = 16B unit (2 experts)
            cpa16(s2u(&sm.Bd[buf][k][c * 2]),
                  &g_gwTdup[(size_t)(kk + k) * NEXP + c * 2]);
        }
        cpa_commit();
    };

    // acc[j][e]: token pair (4ty+2j, 4ty+2j+1), expert 4tx+e
    ull acc[2][4];
#pragma unroll
    for (int j = 0; j < 2; j++)
#pragma unroll
        for (int e = 0; e < 4; e++) acc[j][e] = 0ull;

    fill(0, 0);

    for (int it = 0; it < NIT; it++) {
        if (it + 1 < NIT) { fill((it + 1) & 1, (it + 1) * BK); cpa_wait<1>(); }
        else              { cpa_wait<0>(); }
        __syncthreads();

        const int s = it & 1;
#pragma unroll 4
        for (int k = 0; k < BK; k++) {              // strictly ascending k
            // A: 4 tokens at this k = 2 natural (tok,tok+1) u64 pairs
            float4 av = *reinterpret_cast<const float4*>(
                &sm.At[s][k][4 * ty]);
            ull a0 = *reinterpret_cast<ull*>(&av.x);  // tokens 4ty, 4ty+1
            ull a1 = *reinterpret_cast<ull*>(&av.z);  // tokens 4ty+2, 4ty+3
            // B: 4 duplicated experts = 2x LDS.128
            ulonglong2 b01 = *reinterpret_cast<const ulonglong2*>(
                &sm.Bd[s][k][4 * tx]);
            ulonglong2 b23 = *reinterpret_cast<const ulonglong2*>(
                &sm.Bd[s][k][4 * tx + 2]);
            ffma2(acc[0][0], a0, b01.x);
            ffma2(acc[0][1], a0, b01.y);
            ffma2(acc[0][2], a0, b23.x);
            ffma2(acc[0][3], a0, b23.y);
            ffma2(acc[1][0], a1, b01.x);
            ffma2(acc[1][1], a1, b01.y);
            ffma2(acc[1][2], a1, b23.x);
            ffma2(acc[1][3], a1, b23.y);
        }
        __syncthreads();   // all reads of buf done before next fill overwrites it
    }

    // store logits (aliases At -> already synced above)
#pragma unroll
    for (int j = 0; j < 2; j++)
#pragma unroll
        for (int e = 0; e < 4; e++) {
            float2 v = *reinterpret_cast<float2*>(&acc[j][e]);
            sm.logits[4 * ty + 2 * j]    [4 * tx + e] = v.x;
            sm.logits[4 * ty + 2 * j + 1][4 * tx + e] = v.y;
        }
    __syncthreads();

    // ---- fused epilogue: 1 thread per real token ----
    if (tid < TILE_T && t0 + tid < T) {
        const int t = t0 + tid;
        float* L = sm.logits[tid];

        float mx = -3.4e38f;
#pragma unroll
        for (int e = 0; e < NEXP; e++) mx = fmaxf(mx, L[e]);
        float ssum = 0.f;
        for (int e = 0; e < NEXP; e++) {
            float ex = expf(L[e] - mx);
            L[e] = ex;
            ssum += ex;
        }
        const float inv = 1.f / ssum;

        // top-8 on score + bias; strict '>' == stable tie-break (lower idx wins)
        float tv[8]; int ti[8];
#pragma unroll
        for (int k = 0; k < 8; k++) { tv[k] = -3.4e38f; ti[k] = 0; }
        for (int e = 0; e < NEXP; e++) {
            float v = L[e] * inv + sm.bias[e];
            int idx = e;
#pragma unroll
            for (int k = 0; k < 8; k++) {
                if (v > tv[k]) {
                    float fv = tv[k]; int fi = ti[k];
                    tv[k] = v; ti[k] = idx;
                    v = fv;  idx = fi;
                }
            }
        }

        float pv[8]; float ps = 0.f;
#pragma unroll
        for (int k = 0; k < 8; k++) { pv[k] = L[ti[k]] * inv; ps += pv[k]; }
        const float rn = 1.f / (ps + 1e-9f);

        float* __restrict__ probs = out;
        float* __restrict__ idxo  = out + (size_t)T * 8;
        float* __restrict__ rmap  = out + (size_t)T * 16;
#pragma unroll
        for (int k = 0; k < 8; k++) {
            probs[(size_t)t * 8 + k] = pv[k] * rn;
            idxo [(size_t)t * 8 + k] = (float)ti[k];
        }
        ull mask = 0;
#pragma unroll
        for (int k = 0; k < 8; k++) mask |= (1ull << ti[k]);
        float4* rp = reinterpret_cast<float4*>(&rmap[(size_t)t * 64]);
#pragma unroll
        for (int g = 0; g < 16; g++) {
            float4 vv;
            vv.x = ((mask >> (g * 4 + 0)) & 1ull) ? 1.f : 0.f;
            vv.y = ((mask >> (g * 4 + 1)) & 1ull) ? 1.f : 0.f;
            vv.z = ((mask >> (g * 4 + 2)) & 1ull) ? 1.f : 0.f;
            vv.w = ((mask >> (g * 4 + 3)) & 1ull) ? 1.f : 0.f;
            rp[g] = vv;
        }
    }

    if (blockIdx.x == 0 && tid == 0)
        out[(size_t)T * 80] = 0.f;   // aux_loss
}

extern "C" void kernel_launch(void* const* d_in, const int* in_sizes, int n_in,
                              void* d_out, int out_size)
{
    const float* hs   = (const float*)d_in[0];  // [T, 2048]
    const float* gw   = (const float*)d_in[1];  // [64, 2048]
    const float* bias = (const float*)d_in[2];  // [64]
    const int T = in_sizes[0] / HDIM;

    cudaFuncSetAttribute(router_kernel,
                         cudaFuncAttributeMaxDynamicSharedMemorySize,
                         (int)sizeof(Smem));

    dim3 tg(32, 8);
    dim3 tb(HDIM / 32, NEXP / 32);
    transpose_gw<<<tb, tg>>>(gw);
    router_kernel<<<(T + TILE_T - 1) / TILE_T, 256, sizeof(Smem)>>>(
        hs, bias, (float*)d_out, T);
}

// round 14
// speedup vs baseline: 2.1244x; 2.1244x over previous
#include <cuda_runtime.h>
#include <cuda_bf16.h>
#include <cstdint>

#define HDIM 2048
#define NEXP 64
#define TOPK 8
#define BK   32
#define NIT  (HDIM / BK)     // 64
#define TILE_T 56            // 293 CTAs, one balanced wave

typedef unsigned long long ull;

__device__ __forceinline__ void ffma2(ull &d, ull a, ull b) {
    asm("fma.rn.f32x2 %0, %1, %2, %0;" : "+l"(d) : "l"(a), "l"(b));
}
__device__ __forceinline__ void cpa16(uint32_t s, const void* g) {
    asm volatile("cp.async.cg.shared.global [%0], [%1], 16;" :: "r"(s), "l"(g));
}
__device__ __forceinline__ void cpa_commit() {
    asm volatile("cp.async.commit_group;");
}
template <int N>
__device__ __forceinline__ void cpa_wait() {
    asm volatile("cp.async.wait_group %0;" :: "n"(N));
}
__device__ __forceinline__ uint32_t s2u(const void* p) {
    return (uint32_t)__cvta_generic_to_shared(p);
}

// k-major copy of gate_w: gwT[k][e]
__device__ float g_gwT[HDIM * NEXP];

__global__ void transpose_gw(const float* __restrict__ gw) {
    __shared__ float t[32][33];
    int k0 = blockIdx.x * 32, e0 = blockIdx.y * 32;
#pragma unroll
    for (int r = 0; r < 32; r += 8)
        t[threadIdx.y + r][threadIdx.x] =
            gw[(size_t)(e0 + threadIdx.y + r) * HDIM + k0 + threadIdx.x];
    __syncthreads();
#pragma unroll
    for (int r = 0; r < 32; r += 8)
        g_gwT[(size_t)(k0 + threadIdx.y + r) * NEXP + e0 + threadIdx.x] =
            t[threadIdx.x][threadIdx.y + r];
}

#define ARPAD 36   // floats per Arow row (8 granules + pad)
#define ADPAD 34   // ull per Adup row (272 B: 16B-aligned, mod128=16)

struct Smem {
    union {
        struct {
            float Arow[2][64][ARPAD];   // 18432 B  staging (cp.async target)
            ull   Adup[2][64][ADPAD];   // 34816 B  duplicated A: (v,v) per k
        } mm;
        float logits[64][65];           // aliases after GEMM
    };
    float B[2][BK][NEXP];               // 16384 B  k-major B
    float bias[NEXP];
};
// ~69.9 KB -> 2 CTAs/SM

__global__ __launch_bounds__(128)
void router_kernel(const float* __restrict__ hs,
                   const float* __restrict__ bias,
                   float* __restrict__ out, int T)
{
    extern __shared__ char smem_raw[];
    Smem& sm = *reinterpret_cast<Smem*>(smem_raw);
    const int tid = threadIdx.x;
    const int tx  = tid & 15;        // experts 4tx..4tx+3
    const int ty  = tid >> 4;        // tokens 8ty..8ty+7 (ty 0..7)
    const int t0  = blockIdx.x * TILE_T;

    if (tid < NEXP) sm.bias[tid] = bias[tid];

    auto fillcpa = [&](int buf, int kk) {
        // Arow: 64 tok x 8 granules, coalesced 128B per row-chunk
#pragma unroll
        for (int m = 0; m < 4; m++) {
            int idx = tid + 128 * m;
            int row = idx >> 3, kc = idx & 7;
            int trow = t0 + row; if (trow > T - 1) trow = T - 1;
            cpa16(s2u(&sm.mm.Arow[buf][row][kc * 4]),
                  &hs[(size_t)trow * HDIM + kk + kc * 4]);
        }
        // B: 32 k x 16 granules
#pragma unroll
        for (int m = 0; m < 4; m++) {
            int idx = tid + 128 * m;
            int k = idx >> 4, eg = idx & 15;
            cpa16(s2u(&sm.B[buf][k][eg * 4]),
                  &g_gwT[(size_t)(kk + k) * NEXP + eg * 4]);
        }
        cpa_commit();
    };

    // Arow[buf] -> Adup[buf]: each float v becomes u64 (v,v)
    auto dup = [&](int buf) {
#pragma unroll
        for (int m = 0; m < 4; m++) {
            int idx  = tid + 128 * m;
            int q    = idx >> 5, lane = idx & 31;
            int tok  = (q & 7) * 8 + (lane >> 2);    // 8 toks per STS group
            int kc   = (q >> 3) * 4 + (lane & 3);    // 4 kc per group
            float4 v = *reinterpret_cast<const float4*>(
                &sm.mm.Arow[buf][tok][kc * 4]);
            uint32_t x = __float_as_uint(v.x), y = __float_as_uint(v.y);
            uint32_t z = __float_as_uint(v.z), w = __float_as_uint(v.w);
            uint4 p0 = make_uint4(x, x, y, y);
            uint4 p1 = make_uint4(z, z, w, w);
            *reinterpret_cast<uint4*>(&sm.mm.Adup[buf][tok][kc * 4])     = p0;
            *reinterpret_cast<uint4*>(&sm.mm.Adup[buf][tok][kc * 4 + 2]) = p1;
        }
    };

    // acc[i][p]: token 8ty+i, expert pair (4tx+2p, 4tx+2p+1)
    ull acc[8][2];
#pragma unroll
    for (int i = 0; i < 8; i++) { acc[i][0] = 0ull; acc[i][1] = 0ull; }

    fillcpa(0, 0);
    cpa_wait<0>(); __syncthreads();
    dup(0);

    for (int it = 0; it < NIT; it++) {
        const int buf = it & 1;
        if (it + 1 < NIT) fillcpa(buf ^ 1, (it + 1) * BK);
        __syncthreads();                 // publish Adup[buf] (+ guard Arow reads)

#pragma unroll
        for (int kq = 0; kq < BK / 4; kq++) {       // 4 k's per step
            float4 bq[4];
#pragma unroll
            for (int d = 0; d < 4; d++)
                bq[d] = *reinterpret_cast<const float4*>(
                    &sm.B[buf][kq * 4 + d][4 * tx]);
            ull bl[4], bh[4];
#pragma unroll
            for (int d = 0; d < 4; d++) {
                bl[d] = *reinterpret_cast<ull*>(&bq[d].x);  // (e0,e1)
                bh[d] = *reinterpret_cast<ull*>(&bq[d].z);  // (e2,e3)
            }
#pragma unroll
            for (int i = 0; i < 8; i++) {
                ulonglong2 aA = *reinterpret_cast<const ulonglong2*>(
                    &sm.mm.Adup[buf][8 * ty + i][kq * 4]);      // k0,k1 dup
                ulonglong2 aB = *reinterpret_cast<const ulonglong2*>(
                    &sm.mm.Adup[buf][8 * ty + i][kq * 4 + 2]);  // k2,k3 dup
                ffma2(acc[i][0], aA.x, bl[0]); ffma2(acc[i][1], aA.x, bh[0]);
                ffma2(acc[i][0], aA.y, bl[1]); ffma2(acc[i][1], aA.y, bh[1]);
                ffma2(acc[i][0], aB.x, bl[2]); ffma2(acc[i][1], aB.x, bh[2]);
                ffma2(acc[i][0], aB.y, bl[3]); ffma2(acc[i][1], aB.y, bh[3]);
            }
        }

        if (it + 1 < NIT) {
            cpa_wait<0>(); __syncthreads();   // Arow/B[buf^1] landed; Adup[buf^1] free
            dup(buf ^ 1);
        }
    }

    __syncthreads();   // all compute done before logits alias mm
#pragma unroll
    for (int i = 0; i < 8; i++)
#pragma unroll
        for (int p = 0; p < 2; p++) {
            float2 v = *reinterpret_cast<float2*>(&acc[i][p]);
            sm.logits[8 * ty + i][4 * tx + 2 * p]     = v.x;
            sm.logits[8 * ty + i][4 * tx + 2 * p + 1] = v.y;
        }
    __syncthreads();

    // ---- fused epilogue: 1 thread per real token ----
    if (tid < TILE_T && t0 + tid < T) {
        const int t = t0 + tid;
        float* L = sm.logits[tid];

        float mx = -3.4e38f;
#pragma unroll
        for (int e = 0; e < NEXP; e++) mx = fmaxf(mx, L[e]);
        float ssum = 0.f;
        for (int e = 0; e < NEXP; e++) {
            float ex = expf(L[e] - mx);
            L[e] = ex;
            ssum += ex;
        }
        const float inv = 1.f / ssum;

        float tv[8]; int ti[8];
#pragma unroll
        for (int k = 0; k < 8; k++) { tv[k] = -3.4e38f; ti[k] = 0; }
        for (int e = 0; e < NEXP; e++) {
            float v = L[e] * inv + sm.bias[e];
            int idx = e;
#pragma unroll
            for (int k = 0; k < 8; k++) {
                if (v > tv[k]) {
                    float fv = tv[k]; int fi = ti[k];
                    tv[k] = v; ti[k] = idx;
                    v = fv;  idx = fi;
                }
            }
        }

        float pv[8]; float ps = 0.f;
#pragma unroll
        for (int k = 0; k < 8; k++) { pv[k] = L[ti[k]] * inv; ps += pv[k]; }
        const float rn = 1.f / (ps + 1e-9f);

        float* __restrict__ probs = out;
        float* __restrict__ idxo  = out + (size_t)T * 8;
        float* __restrict__ rmap  = out + (size_t)T * 16;
#pragma unroll
        for (int k = 0; k < 8; k++) {
            probs[(size_t)t * 8 + k] = pv[k] * rn;
            idxo [(size_t)t * 8 + k] = (float)ti[k];
        }
        ull mask = 0;
#pragma unroll
        for (int k = 0; k < 8; k++) mask |= (1ull << ti[k]);
        float4* rp = reinterpret_cast<float4*>(&rmap[(size_t)t * 64]);
#pragma unroll
        for (int g = 0; g < 16; g++) {
            float4 vv;
            vv.x = ((mask >> (g * 4 + 0)) & 1ull) ? 1.f : 0.f;
            vv.y = ((mask >> (g * 4 + 1)) & 1ull) ? 1.f : 0.f;
            vv.z = ((mask >> (g * 4 + 2)) & 1ull) ? 1.f : 0.f;
            vv.w = ((mask >> (g * 4 + 3)) & 1ull) ? 1.f : 0.f;
            rp[g] = vv;
        }
    }

    if (blockIdx.x == 0 && tid == 0)
        out[(size_t)T * 80] = 0.f;   // aux_loss
}

extern "C" void kernel_launch(void* const* d_in, const int* in_sizes, int n_in,
                              void* d_out, int out_size)
{
    const float* hs   = (const float*)d_in[0];  // [T, 2048]
    const float* gw   = (const float*)d_in[1];  // [64, 2048]
    const float* bias = (const float*)d_in[2];  // [64]
    const int T = in_sizes[0] / HDIM;

    cudaFuncSetAttribute(router_kernel,
                         cudaFuncAttributeMaxDynamicSharedMemorySize,
                         (int)sizeof(Smem));

    dim3 tg(32, 8);
    dim3 tb(HDIM / 32, NEXP / 32);
    transpose_gw<<<tb, tg>>>(gw);
    router_kernel<<<(T + TILE_T - 1) / TILE_T, 128, sizeof(Smem)>>>(
        hs, bias, (float*)d_out, T);
}

// round 15
// speedup vs baseline: 2.9592x; 1.3929x over previous
#include <cuda_runtime.h>
#include <cuda_bf16.h>
#include <cstdint>

#define HDIM 2048
#define NEXP 64
#define TOPK 8
#define BK   64
#define NIT  (HDIM / BK)     // 32
#define APAD 68              // floats per A row (272B stride, 16B-aligned)
#define TILE_T 56            // 293 CTAs, one balanced wave
#define NKG  (BK / 2)        // 32 k-groups of 2 k's per tile

typedef unsigned long long ull;

__device__ __forceinline__ void ffma2(ull &d, ull a, ull b) {
    asm("fma.rn.f32x2 %0, %1, %2, %0;" : "+l"(d) : "l"(a), "l"(b));
}
__device__ __forceinline__ ull splat2(float x) {
    ull r; asm("mov.b64 %0, {%1, %1};" : "=l"(r) : "f"(x)); return r;
}
__device__ __forceinline__ void cpa16(uint32_t s, const void* g) {
    asm volatile("cp.async.cg.shared.global [%0], [%1], 16;" :: "r"(s), "l"(g));
}
__device__ __forceinline__ void cpa_commit() {
    asm volatile("cp.async.commit_group;");
}
template <int N>
__device__ __forceinline__ void cpa_wait() {
    asm volatile("cp.async.wait_group %0;" :: "n"(N));
}
__device__ __forceinline__ uint32_t s2u(const void* p) {
    return (uint32_t)__cvta_generic_to_shared(p);
}

// k-major copy of gate_w: gwT[k][e]
__device__ float g_gwT[HDIM * NEXP];

__global__ void transpose_gw(const float* __restrict__ gw) {
    __shared__ float t[32][33];
    int k0 = blockIdx.x * 32, e0 = blockIdx.y * 32;
#pragma unroll
    for (int r = 0; r < 32; r += 8)
        t[threadIdx.y + r][threadIdx.x] =
            gw[(size_t)(e0 + threadIdx.y + r) * HDIM + k0 + threadIdx.x];
    __syncthreads();
#pragma unroll
    for (int r = 0; r < 32; r += 8)
        g_gwT[(size_t)(k0 + threadIdx.y + r) * NEXP + e0 + threadIdx.x] =
            t[threadIdx.x][threadIdx.y + r];
}

struct Smem {
    union {
        float A[2][64][APAD];        // 34816 B  token-major A tiles
        float logits[64][65];        // aliases A after GEMM
    };
    float B[2][BK][NEXP];            // 32768 B  k-major B tiles
    float bias[NEXP];
};
// ~68 KB -> dynamic smem, 2 CTAs/SM

__global__ __launch_bounds__(128)
void router_kernel(const float* __restrict__ hs,
                   const float* __restrict__ bias,
                   float* __restrict__ out, int T)
{
    extern __shared__ char smem_raw[];
    Smem& sm = *reinterpret_cast<Smem*>(smem_raw);
    const int tid = threadIdx.x;
    const int tx  = tid & 15;        // experts 4tx..4tx+3
    const int ty  = tid >> 4;        // tokens 8ty..8ty+7 (ty 0..7)
    const int t0  = blockIdx.x * TILE_T;

    if (tid < NEXP) sm.bias[tid] = bias[tid];

    auto fill = [&](int buf, int kk) {
#pragma unroll
        for (int m = 0; m < 8; m++) {                 // A: 64 rows x 16 granules
            int idx = tid + 128 * m;
            int row = idx >> 4, kc = idx & 15;
            int trow = t0 + row; if (trow > T - 1) trow = T - 1;
            cpa16(s2u(&sm.A[buf][row][kc * 4]),
                  &hs[(size_t)trow * HDIM + kk + kc * 4]);
        }
#pragma unroll
        for (int m = 0; m < 8; m++) {                 // B: 64 k x 16 granules
            int idx = tid + 128 * m;
            int k = idx >> 4, eg = idx & 15;
            cpa16(s2u(&sm.B[buf][k][eg * 4]),
                  &g_gwT[(size_t)(kk + k) * NEXP + eg * 4]);
        }
        cpa_commit();
    };

    // acc[i][p]: token 8ty+i, expert pair (4tx+2p, 4tx+2p+1)
    ull acc[8][2];
#pragma unroll
    for (int i = 0; i < 8; i++) { acc[i][0] = 0ull; acc[i][1] = 0ull; }

    // double-buffered operand registers for the KG software pipeline
    float2 areg[2][8];               // a[i] = A[row][2k..2k+1]
    float4 breg[2][2];               // b[j] = B[2k+j][4tx..4tx+3]

    auto loadKG = [&](int s, int kg, int slot) {
        const int k0 = kg * 2;
#pragma unroll
        for (int i = 0; i < 8; i++)
            areg[slot][i] = *reinterpret_cast<const float2*>(
                &sm.A[s][8 * ty + i][k0]);
        breg[slot][0] = *reinterpret_cast<const float4*>(&sm.B[s][k0][4 * tx]);
        breg[slot][1] = *reinterpret_cast<const float4*>(&sm.B[s][k0 + 1][4 * tx]);
    };
    auto computeKG = [&](int slot) {
        ull bl0 = *reinterpret_cast<ull*>(&breg[slot][0].x);
        ull bh0 = *reinterpret_cast<ull*>(&breg[slot][0].z);
        ull bl1 = *reinterpret_cast<ull*>(&breg[slot][1].x);
        ull bh1 = *reinterpret_cast<ull*>(&breg[slot][1].z);
#pragma unroll
        for (int i = 0; i < 8; i++) {                // k even then k odd: ascending
            ull a0 = splat2(areg[slot][i].x);
            ffma2(acc[i][0], a0, bl0);
            ffma2(acc[i][1], a0, bh0);
        }
#pragma unroll
        for (int i = 0; i < 8; i++) {
            ull a1 = splat2(areg[slot][i].y);
            ffma2(acc[i][0], a1, bl1);
            ffma2(acc[i][1], a1, bh1);
        }
    };

    fill(0, 0);

    for (int it = 0; it < NIT; it++) {
        if (it + 1 < NIT) { fill((it + 1) & 1, (it + 1) * BK); cpa_wait<1>(); }
        else              { cpa_wait<0>(); }
        __syncthreads();

        const int s = it & 1;
        loadKG(s, 0, 0);                      // prime the pipeline
#pragma unroll
        for (int g = 0; g < NKG; g++) {
            const int cur = g & 1;
            if (g + 1 < NKG) loadKG(s, g + 1, cur ^ 1);  // prefetch next KG
            computeKG(cur);                               // compute current KG
        }
        __syncthreads();   // all reads of buf done before next fill overwrites it
    }

    // store logits (aliases A -> already synced above)
#pragma unroll
    for (int i = 0; i < 8; i++)
#pragma unroll
        for (int p = 0; p < 2; p++) {
            float2 v = *reinterpret_cast<float2*>(&acc[i][p]);
            sm.logits[8 * ty + i][4 * tx + 2 * p]     = v.x;
            sm.logits[8 * ty + i][4 * tx + 2 * p + 1] = v.y;
        }
    __syncthreads();

    // ---- fused epilogue: 1 thread per real token ----
    if (tid < TILE_T && t0 + tid < T) {
        const int t = t0 + tid;
        float* L = sm.logits[tid];

        float mx = -3.4e38f;
#pragma unroll
        for (int e = 0; e < NEXP; e++) mx = fmaxf(mx, L[e]);
        float ssum = 0.f;
        for (int e = 0; e < NEXP; e++) {
            float ex = expf(L[e] - mx);
            L[e] = ex;
            ssum += ex;
        }
        const float inv = 1.f / ssum;

        // top-8 on score + bias; strict '>' == stable tie-break (lower idx wins)
        float tv[8]; int ti[8];
#pragma unroll
        for (int k = 0; k < 8; k++) { tv[k] = -3.4e38f; ti[k] = 0; }
        for (int e = 0; e < NEXP; e++) {
            float v = L[e] * inv + sm.bias[e];
            int idx = e;
#pragma unroll
            for (int k = 0; k < 8; k++) {
                if (v > tv[k]) {
                    float fv = tv[k]; int fi = ti[k];
                    tv[k] = v; ti[k] = idx;
                    v = fv;  idx = fi;
                }
            }
        }

        float pv[8]; float ps = 0.f;
#pragma unroll
        for (int k = 0; k < 8; k++) { pv[k] = L[ti[k]] * inv; ps += pv[k]; }
        const float rn = 1.f / (ps + 1e-9f);

        float* __restrict__ probs = out;
        float* __restrict__ idxo  = out + (size_t)T * 8;
        float* __restrict__ rmap  = out + (size_t)T * 16;
#pragma unroll
        for (int k = 0; k < 8; k++) {
            probs[(size_t)t * 8 + k] = pv[k] * rn;
            idxo [(size_t)t * 8 + k] = (float)ti[k];
        }
        ull mask = 0;
#pragma unroll
        for (int k = 0; k < 8; k++) mask |= (1ull << ti[k]);
        float4* rp = reinterpret_cast<float4*>(&rmap[(size_t)t * 64]);
#pragma unroll
        for (int g = 0; g < 16; g++) {
            float4 vv;
            vv.x = ((mask >> (g * 4 + 0)) & 1ull) ? 1.f : 0.f;
            vv.y = ((mask >> (g * 4 + 1)) & 1ull) ? 1.f : 0.f;
            vv.z = ((mask >> (g * 4 + 2)) & 1ull) ? 1.f : 0.f;
            vv.w = ((mask >> (g * 4 + 3)) & 1ull) ? 1.f : 0.f;
            rp[g] = vv;
        }
    }

    if (blockIdx.x == 0 && tid == 0)
        out[(size_t)T * 80] = 0.f;   // aux_loss
}

extern "C" void kernel_launch(void* const* d_in, const int* in_sizes, int n_in,
                              void* d_out, int out_size)
{
    const float* hs   = (const float*)d_in[0];  // [T, 2048]
    const float* gw   = (const float*)d_in[1];  // [64, 2048]
    const float* bias = (const float*)d_in[2];  // [64]
    const int T = in_sizes[0] / HDIM;

    cudaFuncSetAttribute(router_kernel,
                         cudaFuncAttributeMaxDynamicSharedMemorySize,
                         (int)sizeof(Smem));

    dim3 tg(32, 8);
    dim3 tb(HDIM / 32, NEXP / 32);
    transpose_gw<<<tb, tg>>>(gw);
    router_kernel<<<(T + TILE_T - 1) / TILE_T, 128, sizeof(Smem)>>>(
        hs, bias, (float*)d_out, T);
}

// round 16
// speedup vs baseline: 3.0101x; 1.0172x over previous
#include <cuda_runtime.h>
#include <cuda_bf16.h>
#include <cstdint>

#define HDIM 2048
#define NEXP 64
#define TOPK 8
#define BK   64
#define NIT  (HDIM / BK)     // 32
#define APAD 68              // floats per A row (272B stride, 16B-aligned)
#define TILE_T 56            // 293 CTAs, one balanced wave
#define NKQ  (BK / 4)        // 16 k-quads per tile

typedef unsigned long long ull;

__device__ __forceinline__ void ffma2(ull &d, ull a, ull b) {
    asm("fma.rn.f32x2 %0, %1, %2, %0;" : "+l"(d) : "l"(a), "l"(b));
}
__device__ __forceinline__ ull splat2(float x) {
    ull r; asm("mov.b64 %0, {%1, %1};" : "=l"(r) : "f"(x)); return r;
}
__device__ __forceinline__ void cpa16(uint32_t s, const void* g) {
    asm volatile("cp.async.cg.shared.global [%0], [%1], 16;" :: "r"(s), "l"(g));
}
__device__ __forceinline__ void cpa_commit() {
    asm volatile("cp.async.commit_group;");
}
template <int N>
__device__ __forceinline__ void cpa_wait() {
    asm volatile("cp.async.wait_group %0;" :: "n"(N));
}
__device__ __forceinline__ uint32_t s2u(const void* p) {
    return (uint32_t)__cvta_generic_to_shared(p);
}

// k-major copy of gate_w: gwT[k][e]
__device__ float g_gwT[HDIM * NEXP];

__global__ void transpose_gw(const float* __restrict__ gw) {
    __shared__ float t[32][33];
    int k0 = blockIdx.x * 32, e0 = blockIdx.y * 32;
#pragma unroll
    for (int r = 0; r < 32; r += 8)
        t[threadIdx.y + r][threadIdx.x] =
            gw[(size_t)(e0 + threadIdx.y + r) * HDIM + k0 + threadIdx.x];
    __syncthreads();
#pragma unroll
    for (int r = 0; r < 32; r += 8)
        g_gwT[(size_t)(k0 + threadIdx.y + r) * NEXP + e0 + threadIdx.x] =
            t[threadIdx.x][threadIdx.y + r];
}

struct Smem {
    union {
        float A[2][64][APAD];        // 34816 B  token-major A tiles
        float logits[64][65];        // aliases A after GEMM
    };
    float B[2][BK][NEXP];            // 32768 B  k-major B tiles
    float bias[NEXP];
};
// ~68 KB -> dynamic smem, 2 CTAs/SM

__global__ __launch_bounds__(128, 2)   // 2 CTAs/SM guaranteed; up to 256 regs
void router_kernel(const float* __restrict__ hs,
                   const float* __restrict__ bias,
                   float* __restrict__ out, int T)
{
    extern __shared__ char smem_raw[];
    Smem& sm = *reinterpret_cast<Smem*>(smem_raw);
    const int tid = threadIdx.x;
    const int tx  = tid & 15;        // experts 4tx..4tx+3
    const int ty  = tid >> 4;        // tokens 8ty..8ty+7 (ty 0..7)
    const int t0  = blockIdx.x * TILE_T;

    if (tid < NEXP) sm.bias[tid] = bias[tid];

    auto fill = [&](int buf, int kk) {
#pragma unroll
        for (int m = 0; m < 8; m++) {                 // A: 64 rows x 16 granules
            int idx = tid + 128 * m;
            int row = idx >> 4, kc = idx & 15;
            int trow = t0 + row; if (trow > T - 1) trow = T - 1;
            cpa16(s2u(&sm.A[buf][row][kc * 4]),
                  &hs[(size_t)trow * HDIM + kk + kc * 4]);
        }
#pragma unroll
        for (int m = 0; m < 8; m++) {                 // B: 64 k x 16 granules
            int idx = tid + 128 * m;
            int k = idx >> 4, eg = idx & 15;
            cpa16(s2u(&sm.B[buf][k][eg * 4]),
                  &g_gwT[(size_t)(kk + k) * NEXP + eg * 4]);
        }
        cpa_commit();
    };

    // acc[i][p]: token 8ty+i, expert pair (4tx+2p, 4tx+2p+1)
    ull acc[8][2];
#pragma unroll
    for (int i = 0; i < 8; i++) { acc[i][0] = 0ull; acc[i][1] = 0ull; }

    // double-buffered operand registers, kq (4-k) granularity
    float4 areg[2][8];               // a[i] = A[row][4kq..4kq+3]
    float4 breg[2][4];               // b[d] = B[4kq+d][4tx..4tx+3]

    auto loadKQ = [&](int s, int kq, int slot) {
#pragma unroll
        for (int i = 0; i < 8; i++)
            areg[slot][i] = *reinterpret_cast<const float4*>(
                &sm.A[s][8 * ty + i][kq * 4]);
#pragma unroll
        for (int d = 0; d < 4; d++)
            breg[slot][d] = *reinterpret_cast<const float4*>(
                &sm.B[s][kq * 4 + d][4 * tx]);
    };
    auto computeKQ = [&](int slot) {
#pragma unroll
        for (int d = 0; d < 4; d++) {               // ascending k
            ull bl = *reinterpret_cast<ull*>(&breg[slot][d].x);
            ull bh = *reinterpret_cast<ull*>(&breg[slot][d].z);
#pragma unroll
            for (int i = 0; i < 8; i++) {
                const float av = (d == 0) ? areg[slot][i].x
                               : (d == 1) ? areg[slot][i].y
                               : (d == 2) ? areg[slot][i].z
                               :            areg[slot][i].w;
                ull as = splat2(av);
                ffma2(acc[i][0], as, bl);
                ffma2(acc[i][1], as, bh);
            }
        }
    };

    fill(0, 0);

    for (int it = 0; it < NIT; it++) {
        if (it + 1 < NIT) { fill((it + 1) & 1, (it + 1) * BK); cpa_wait<1>(); }
        else              { cpa_wait<0>(); }
        __syncthreads();

        const int s = it & 1;
        loadKQ(s, 0, 0);                       // prime
#pragma unroll
        for (int kq = 0; kq < NKQ; kq++) {
            const int cur = kq & 1;
            if (kq + 1 < NKQ) loadKQ(s, kq + 1, cur ^ 1);   // prefetch next
            computeKQ(cur);
        }
        __syncthreads();   // all reads of buf done before next fill overwrites it
    }

    // store logits (aliases A -> already synced above)
#pragma unroll
    for (int i = 0; i < 8; i++)
#pragma unroll
        for (int p = 0; p < 2; p++) {
            float2 v = *reinterpret_cast<float2*>(&acc[i][p]);
            sm.logits[8 * ty + i][4 * tx + 2 * p]     = v.x;
            sm.logits[8 * ty + i][4 * tx + 2 * p + 1] = v.y;
        }
    __syncthreads();

    // ---- fused epilogue: 1 thread per real token ----
    if (tid < TILE_T && t0 + tid < T) {
        const int t = t0 + tid;
        float* L = sm.logits[tid];

        float mx = -3.4e38f;
#pragma unroll
        for (int e = 0; e < NEXP; e++) mx = fmaxf(mx, L[e]);
        float ssum = 0.f;
        for (int e = 0; e < NEXP; e++) {
            float ex = expf(L[e] - mx);
            L[e] = ex;
            ssum += ex;
        }
        const float inv = 1.f / ssum;

        // top-8 on score + bias; strict '>' == stable tie-break (lower idx wins)
        float tv[8]; int ti[8];
#pragma unroll
        for (int k = 0; k < 8; k++) { tv[k] = -3.4e38f; ti[k] = 0; }
        for (int e = 0; e < NEXP; e++) {
            float v = L[e] * inv + sm.bias[e];
            int idx = e;
#pragma unroll
            for (int k = 0; k < 8; k++) {
                if (v > tv[k]) {
                    float fv = tv[k]; int fi = ti[k];
                    tv[k] = v; ti[k] = idx;
                    v = fv;  idx = fi;
                }
            }
        }

        float pv[8]; float ps = 0.f;
#pragma unroll
        for (int k = 0; k < 8; k++) { pv[k] = L[ti[k]] * inv; ps += pv[k]; }
        const float rn = 1.f / (ps + 1e-9f);

        float* __restrict__ probs = out;
        float* __restrict__ idxo  = out + (size_t)T * 8;
        float* __restrict__ rmap  = out + (size_t)T * 16;
#pragma unroll
        for (int k = 0; k < 8; k++) {
            probs[(size_t)t * 8 + k] = pv[k] * rn;
            idxo [(size_t)t * 8 + k] = (float)ti[k];
        }
        ull mask = 0;
#pragma unroll
        for (int k = 0; k < 8; k++) mask |= (1ull << ti[k]);
        float4* rp = reinterpret_cast<float4*>(&rmap[(size_t)t * 64]);
#pragma unroll
        for (int g = 0; g < 16; g++) {
            float4 vv;
            vv.x = ((mask >> (g * 4 + 0)) & 1ull) ? 1.f : 0.f;
            vv.y = ((mask >> (g * 4 + 1)) & 1ull) ? 1.f : 0.f;
            vv.z = ((mask >> (g * 4 + 2)) & 1ull) ? 1.f : 0.f;
            vv.w = ((mask >> (g * 4 + 3)) & 1ull) ? 1.f : 0.f;
            rp[g] = vv;
        }
    }

    if (blockIdx.x == 0 && tid == 0)
        out[(size_t)T * 80] = 0.f;   // aux_loss
}

extern "C" void kernel_launch(void* const* d_in, const int* in_sizes, int n_in,
                              void* d_out, int out_size)
{
    const float* hs   = (const float*)d_in[0];  // [T, 2048]
    const float* gw   = (const float*)d_in[1];  // [64, 2048]
    const float* bias = (const float*)d_in[2];  // [64]
    const int T = in_sizes[0] / HDIM;

    cudaFuncSetAttribute(router_kernel,
                         cudaFuncAttributeMaxDynamicSharedMemorySize,
                         (int)sizeof(Smem));

    dim3 tg(32, 8);
    dim3 tb(HDIM / 32, NEXP / 32);
    transpose_gw<<<tb, tg>>>(gw);
    router_kernel<<<(T + TILE_T - 1) / TILE_T, 128, sizeof(Smem)>>>(
        hs, bias, (float*)d_out, T);
}